// round 3
// baseline (speedup 1.0000x reference)
#include <cuda_runtime.h>
#include <cuda_bf16.h>
#include <math.h>
#include <stdint.h>

#define N_ROWS 8192
#define DIM    1024
#define BM     128
#define BN     128
#define BK     32
#define SSTRIDE 40   // padded bf16 elements per smem row (80B) -> conflict-free ldmatrix

// Scratch (no cudaMalloc allowed): normalized bf16 copies + max accumulators.
__device__ __nv_bfloat16 g_exn[(size_t)N_ROWS * DIM];
__device__ __nv_bfloat16 g_eyn[(size_t)N_ROWS * DIM];
__device__ float g_rowmax[N_ROWS];
__device__ float g_colmax[N_ROWS];

// float atomic max via signed/unsigned int trick (valid for any sign mix).
__device__ __forceinline__ void atomicMaxF(float* addr, float val) {
    if (__float_as_int(val) >= 0) {
        atomicMax(reinterpret_cast<int*>(addr), __float_as_int(val));
    } else {
        atomicMin(reinterpret_cast<unsigned int*>(addr), __float_as_uint(val));
    }
}

// ---------------------------------------------------------------------------
// Kernel 0: reset max accumulators (runs every launch; graph replays re-run it)
// ---------------------------------------------------------------------------
__global__ void init_kernel() {
    int i = blockIdx.x * blockDim.x + threadIdx.x;   // 0 .. 16383
    if (i < N_ROWS) g_rowmax[i] = -INFINITY;
    else            g_colmax[i - N_ROWS] = -INFINITY;
}

// ---------------------------------------------------------------------------
// Kernel 1: fp32 row L2-normalize, emit bf16. One block per row (16384 rows).
// 256 threads * 4 floats = 1024 elements per row.
// ---------------------------------------------------------------------------
__global__ void __launch_bounds__(256) normalize_kernel(const float* __restrict__ ex,
                                                        const float* __restrict__ ey) {
    __shared__ float sh[8];
    int row = blockIdx.x;
    const float* src;
    __nv_bfloat16* dst;
    if (row < N_ROWS) {
        src = ex + (size_t)row * DIM;
        dst = g_exn + (size_t)row * DIM;
    } else {
        src = ey + (size_t)(row - N_ROWS) * DIM;
        dst = g_eyn + (size_t)(row - N_ROWS) * DIM;
    }
    int tid = threadIdx.x;
    float4 v = reinterpret_cast<const float4*>(src)[tid];
    float ss = v.x * v.x + v.y * v.y + v.z * v.z + v.w * v.w;
    #pragma unroll
    for (int o = 16; o; o >>= 1) ss += __shfl_xor_sync(0xffffffffu, ss, o);
    if ((tid & 31) == 0) sh[tid >> 5] = ss;
    __syncthreads();
    float tot = 0.f;
    #pragma unroll
    for (int w = 0; w < 8; w++) tot += sh[w];
    // norms of N(0,1) rows are ~32, far above eps=1e-8: plain reciprocal sqrt.
    float inv = rsqrtf(tot);
    __nv_bfloat162 p0 = __floats2bfloat162_rn(v.x * inv, v.y * inv);
    __nv_bfloat162 p1 = __floats2bfloat162_rn(v.z * inv, v.w * inv);
    reinterpret_cast<__nv_bfloat162*>(dst)[tid * 2 + 0] = p0;
    reinterpret_cast<__nv_bfloat162*>(dst)[tid * 2 + 1] = p1;
}

// ---------------------------------------------------------------------------
// Kernel 2: 128x128 tile of C = Xn * Yn^T via bf16 mma.sync, fused max-reduce.
// 8 warps: 4 warp-rows x 2 warp-cols; each warp: 32x64 output (2x8 m16n8 tiles).
// ---------------------------------------------------------------------------
__global__ void __launch_bounds__(256) gemm_max_kernel() {
    __shared__ __nv_bfloat16 sA[BM * SSTRIDE];
    __shared__ __nv_bfloat16 sB[BN * SSTRIDE];
    __shared__ float s_rmax[BM];
    __shared__ float s_cmax[BN];

    const int tid  = threadIdx.x;
    const int lane = tid & 31;
    const int wid  = tid >> 5;
    const int warpRow = wid & 3;   // 0..3 -> 32-row slab
    const int warpCol = wid >> 2;  // 0..1 -> 64-col slab
    const int rowBase = blockIdx.y * BM;   // ex rows
    const int colBase = blockIdx.x * BN;   // ey rows

    if (tid < BM) s_rmax[tid] = -INFINITY;
    else          s_cmax[tid - BM] = -INFINITY;

    float acc[2][8][4];
    #pragma unroll
    for (int i = 0; i < 2; i++)
        #pragma unroll
        for (int j = 0; j < 8; j++)
            #pragma unroll
            for (int r = 0; r < 4; r++) acc[i][j][r] = 0.f;

    for (int kt = 0; kt < DIM; kt += BK) {
        // Load 128x32 bf16 tiles of A and B (uint4 = 8 bf16 per thread-op).
        #pragma unroll
        for (int i = 0; i < 2; i++) {
            int v = tid + i * 256;       // 0..511
            int r = v >> 2;              // 0..127
            int c = (v & 3) << 3;        // 0,8,16,24
            *reinterpret_cast<uint4*>(&sA[r * SSTRIDE + c]) =
                *reinterpret_cast<const uint4*>(&g_exn[(size_t)(rowBase + r) * DIM + kt + c]);
            *reinterpret_cast<uint4*>(&sB[r * SSTRIDE + c]) =
                *reinterpret_cast<const uint4*>(&g_eyn[(size_t)(colBase + r) * DIM + kt + c]);
        }
        __syncthreads();

        #pragma unroll
        for (int kk = 0; kk < BK; kk += 16) {
            uint32_t a[2][4];
            uint32_t b[8][2];
            // A fragments: 2 m-tiles, ldmatrix x4 each (16x16 bf16).
            #pragma unroll
            for (int i = 0; i < 2; i++) {
                int r = warpRow * 32 + i * 16 + (lane & 15);
                int c = kk + ((lane >> 4) << 3);
                uint32_t addr = (uint32_t)__cvta_generic_to_shared(&sA[r * SSTRIDE + c]);
                asm volatile("ldmatrix.sync.aligned.m8n8.x4.shared.b16 {%0,%1,%2,%3}, [%4];"
                             : "=r"(a[i][0]), "=r"(a[i][1]), "=r"(a[i][2]), "=r"(a[i][3])
                             : "r"(addr));
            }
            // B fragments: 8 n-tiles, 2 per ldmatrix x4 (B stored [n][k] row-major
            // == col-major KxN, so non-trans ldmatrix matches mma .col B layout).
            #pragma unroll
            for (int j = 0; j < 4; j++) {
                int r = warpCol * 64 + j * 16 + ((lane >> 4) << 3) + (lane & 7);
                int c = kk + (((lane >> 3) & 1) << 3);
                uint32_t addr = (uint32_t)__cvta_generic_to_shared(&sB[r * SSTRIDE + c]);
                asm volatile("ldmatrix.sync.aligned.m8n8.x4.shared.b16 {%0,%1,%2,%3}, [%4];"
                             : "=r"(b[2 * j][0]), "=r"(b[2 * j][1]),
                               "=r"(b[2 * j + 1][0]), "=r"(b[2 * j + 1][1])
                             : "r"(addr));
            }
            #pragma unroll
            for (int i = 0; i < 2; i++)
                #pragma unroll
                for (int j = 0; j < 8; j++)
                    asm volatile(
                        "mma.sync.aligned.m16n8k16.row.col.f32.bf16.bf16.f32 "
                        "{%0,%1,%2,%3}, {%4,%5,%6,%7}, {%8,%9}, {%0,%1,%2,%3};"
                        : "+f"(acc[i][j][0]), "+f"(acc[i][j][1]),
                          "+f"(acc[i][j][2]), "+f"(acc[i][j][3])
                        : "r"(a[i][0]), "r"(a[i][1]), "r"(a[i][2]), "r"(a[i][3]),
                          "r"(b[j][0]), "r"(b[j][1]));
        }
        __syncthreads();
    }

    // ---- Row maxes: thread covers 4 rows x 16 cols; reduce cols in-thread,
    // then over the 4-lane group (xor 1,2), stage via shared atomics.
    #pragma unroll
    for (int i = 0; i < 2; i++) {
        #pragma unroll
        for (int half = 0; half < 2; half++) {
            float m = -INFINITY;
            #pragma unroll
            for (int j = 0; j < 8; j++)
                m = fmaxf(m, fmaxf(acc[i][j][half * 2], acc[i][j][half * 2 + 1]));
            m = fmaxf(m, __shfl_xor_sync(0xffffffffu, m, 1));
            m = fmaxf(m, __shfl_xor_sync(0xffffffffu, m, 2));
            if ((lane & 3) == 0)
                atomicMaxF(&s_rmax[warpRow * 32 + i * 16 + half * 8 + (lane >> 2)], m);
        }
    }
    // ---- Col maxes: per (j, parity) reduce 4 rows in-thread, then over
    // lanes sharing lane&3 (xor 4,8,16).
    #pragma unroll
    for (int j = 0; j < 8; j++) {
        #pragma unroll
        for (int q = 0; q < 2; q++) {
            float m = fmaxf(fmaxf(acc[0][j][q], acc[0][j][q + 2]),
                            fmaxf(acc[1][j][q], acc[1][j][q + 2]));
            m = fmaxf(m, __shfl_xor_sync(0xffffffffu, m, 4));
            m = fmaxf(m, __shfl_xor_sync(0xffffffffu, m, 8));
            m = fmaxf(m, __shfl_xor_sync(0xffffffffu, m, 16));
            if (lane < 4)
                atomicMaxF(&s_cmax[warpCol * 64 + j * 8 + lane * 2 + q], m);
        }
    }
    __syncthreads();
    if (tid < BM) atomicMaxF(&g_rowmax[rowBase + tid], s_rmax[tid]);
    else          atomicMaxF(&g_colmax[colBase + tid - BM], s_cmax[tid - BM]);
}

// ---------------------------------------------------------------------------
// Kernel 3: sum the max vectors, apply entropy transform, write out[2].
// ---------------------------------------------------------------------------
__global__ void __launch_bounds__(256) finalize_kernel(float* __restrict__ out) {
    __shared__ float sh[16];
    int tid = threadIdx.x;
    float sr = 0.f, sc = 0.f;
    for (int i = tid; i < N_ROWS; i += 256) {
        sr += g_rowmax[i];
        sc += g_colmax[i];
    }
    #pragma unroll
    for (int o = 16; o; o >>= 1) {
        sr += __shfl_xor_sync(0xffffffffu, sr, o);
        sc += __shfl_xor_sync(0xffffffffu, sc, o);
    }
    if ((tid & 31) == 0) {
        sh[tid >> 5]     = sr;
        sh[8 + (tid >> 5)] = sc;
    }
    __syncthreads();
    if (tid == 0) {
        float SR = 0.f, SC = 0.f;
        #pragma unroll
        for (int w = 0; w < 8; w++) { SR += sh[w]; SC += sh[8 + w]; }
        const double sigma = 0.3;
        float hc = (float)(0.5 * log(6.283185307179586 * sigma * sigma) + 0.5);
        out[0] = hc * ((float)N_ROWS - SR) / 0.3f;
        out[1] = hc * ((float)N_ROWS - SC) / 0.3f;
    }
}

// ---------------------------------------------------------------------------
extern "C" void kernel_launch(void* const* d_in, const int* in_sizes, int n_in,
                              void* d_out, int out_size) {
    const float* ex = (const float*)d_in[0];
    const float* ey = (const float*)d_in[1];
    float* out = (float*)d_out;

    init_kernel<<<(2 * N_ROWS) / 256, 256>>>();
    normalize_kernel<<<2 * N_ROWS, 256>>>(ex, ey);
    dim3 grid(N_ROWS / BN, N_ROWS / BM);
    gemm_max_kernel<<<grid, 256>>>();
    finalize_kernel<<<1, 256>>>(out);
}

// round 5
// speedup vs baseline: 1.3049x; 1.3049x over previous
#include <cuda_runtime.h>
#include <cuda_bf16.h>
#include <math.h>
#include <stdint.h>

#define N_ROWS 8192
#define DIM    1024
#define BM     128          // CTA rows (ex)
#define BN     256          // CTA cols (ey)
#define BK     64           // k elements per pipeline chunk
#define NCHUNK (DIM / BK)   // 16
#define NSTAGE 3
#define SSTRIDE 72          // padded bf16 elems per smem row (144B) -> conflict-free
#define A_STAGE_BYTES (BM * SSTRIDE * 2)              // 18432
#define B_STAGE_BYTES (BN * SSTRIDE * 2)              // 36864
#define STAGE_BYTES   (A_STAGE_BYTES + B_STAGE_BYTES) // 55296
#define SMEM_PIPE     (NSTAGE * STAGE_BYTES)          // 165888
#define RMAX_OFF      SMEM_PIPE                       // 128 floats
#define CMAX_OFF      (SMEM_PIPE + 512)               // 256 floats
#define SMEM_DYN      (SMEM_PIPE + 512 + 1024)

// Scratch (no cudaMalloc allowed)
__device__ __nv_bfloat16 g_exn[(size_t)N_ROWS * DIM];
__device__ __nv_bfloat16 g_eyn[(size_t)N_ROWS * DIM];
__device__ float g_rowmax[N_ROWS];
__device__ float g_colmax[N_ROWS];

__device__ __forceinline__ void atomicMaxF(float* addr, float val) {
    if (__float_as_int(val) >= 0) {
        atomicMax(reinterpret_cast<int*>(addr), __float_as_int(val));
    } else {
        atomicMin(reinterpret_cast<unsigned int*>(addr), __float_as_uint(val));
    }
}

__device__ __forceinline__ void cp_async16(uint32_t s, const void* g) {
    asm volatile("cp.async.cg.shared.global [%0], [%1], 16;" :: "r"(s), "l"(g));
}
__device__ __forceinline__ void cp_commit() {
    asm volatile("cp.async.commit_group;" ::: "memory");
}
template <int N>
__device__ __forceinline__ void cp_wait() {
    asm volatile("cp.async.wait_group %0;" :: "n"(N) : "memory");
}

// ---------------------------------------------------------------------------
// Kernel 0: reset max accumulators
// ---------------------------------------------------------------------------
__global__ void init_kernel() {
    int i = blockIdx.x * blockDim.x + threadIdx.x;
    if (i < N_ROWS) g_rowmax[i] = -INFINITY;
    else            g_colmax[i - N_ROWS] = -INFINITY;
}

// ---------------------------------------------------------------------------
// Kernel 1: fp32 row L2-normalize, emit bf16.
// ---------------------------------------------------------------------------
__global__ void __launch_bounds__(256) normalize_kernel(const float* __restrict__ ex,
                                                        const float* __restrict__ ey) {
    __shared__ float sh[8];
    int row = blockIdx.x;
    const float* src;
    __nv_bfloat16* dst;
    if (row < N_ROWS) {
        src = ex + (size_t)row * DIM;
        dst = g_exn + (size_t)row * DIM;
    } else {
        src = ey + (size_t)(row - N_ROWS) * DIM;
        dst = g_eyn + (size_t)(row - N_ROWS) * DIM;
    }
    int tid = threadIdx.x;
    float4 v = reinterpret_cast<const float4*>(src)[tid];
    float ss = v.x * v.x + v.y * v.y + v.z * v.z + v.w * v.w;
    #pragma unroll
    for (int o = 16; o; o >>= 1) ss += __shfl_xor_sync(0xffffffffu, ss, o);
    if ((tid & 31) == 0) sh[tid >> 5] = ss;
    __syncthreads();
    float tot = 0.f;
    #pragma unroll
    for (int w = 0; w < 8; w++) tot += sh[w];
    float inv = rsqrtf(tot);
    __nv_bfloat162 p0 = __floats2bfloat162_rn(v.x * inv, v.y * inv);
    __nv_bfloat162 p1 = __floats2bfloat162_rn(v.z * inv, v.w * inv);
    reinterpret_cast<__nv_bfloat162*>(dst)[tid * 2 + 0] = p0;
    reinterpret_cast<__nv_bfloat162*>(dst)[tid * 2 + 1] = p1;
}

// ---------------------------------------------------------------------------
// Kernel 2: pipelined bf16 mma.sync GEMM (128x256 CTA tile), fused max-reduce.
// 8 warps: 2 warp-rows x 4 warp-cols; each warp computes 64x64.
// 3-stage cp.async pipeline over BK=64 chunks.
// ---------------------------------------------------------------------------
__device__ __forceinline__ void load_chunk(uint32_t sbase, int s, int kc,
                                           int rowBase, int colBase, int tid) {
    uint32_t stA = sbase + s * STAGE_BYTES;
    uint32_t stB = stA + A_STAGE_BYTES;
    const __nv_bfloat16* gA = g_exn + (size_t)rowBase * DIM + kc * BK;
    const __nv_bfloat16* gB = g_eyn + (size_t)colBase * DIM + kc * BK;
    #pragma unroll
    for (int t = 0; t < 4; t++) {           // A: 128 rows x 64 elems
        int idx = tid + t * 256;            // 0..1023
        int r = idx >> 3;                   // 0..127
        int c = idx & 7;                    // 16B unit
        cp_async16(stA + r * (SSTRIDE * 2) + c * 16, gA + (size_t)r * DIM + c * 8);
    }
    #pragma unroll
    for (int t = 0; t < 8; t++) {           // B: 256 rows x 64 elems
        int idx = tid + t * 256;            // 0..2047
        int r = idx >> 3;                   // 0..255
        int c = idx & 7;
        cp_async16(stB + r * (SSTRIDE * 2) + c * 16, gB + (size_t)r * DIM + c * 8);
    }
}

__global__ void __launch_bounds__(256, 1) gemm_max_kernel() {
    extern __shared__ char dsm[];
    const int tid  = threadIdx.x;
    const int lane = tid & 31;
    const int wid  = tid >> 5;
    const int warpRow = wid & 1;      // 0..1 -> 64-row slab
    const int warpCol = wid >> 1;     // 0..3 -> 64-col slab
    const int rowBase = blockIdx.y * BM;
    const int colBase = blockIdx.x * BN;

    uint32_t sbase = (uint32_t)__cvta_generic_to_shared(dsm);
    float* s_rmax = reinterpret_cast<float*>(dsm + RMAX_OFF);
    float* s_cmax = reinterpret_cast<float*>(dsm + CMAX_OFF);
    if (tid < BM) s_rmax[tid] = -INFINITY;
    s_cmax[tid] = -INFINITY;

    float acc[4][8][4];
    #pragma unroll
    for (int i = 0; i < 4; i++)
        #pragma unroll
        for (int j = 0; j < 8; j++)
            #pragma unroll
            for (int r = 0; r < 4; r++) acc[i][j][r] = 0.f;

    // prologue: stages 0,1
    load_chunk(sbase, 0, 0, rowBase, colBase, tid); cp_commit();
    load_chunk(sbase, 1, 1, rowBase, colBase, tid); cp_commit();

    for (int ch = 0; ch < NCHUNK; ch++) {
        int s = ch % NSTAGE;
        if (ch < NCHUNK - 1) cp_wait<1>(); else cp_wait<0>();
        __syncthreads();

        // issue next loads first so they overlap this chunk's MMAs
        if (ch + 2 < NCHUNK) {
            load_chunk(sbase, (ch + 2) % NSTAGE, ch + 2, rowBase, colBase, tid);
            cp_commit();
        }

        uint32_t stA = sbase + s * STAGE_BYTES;
        uint32_t stB = stA + A_STAGE_BYTES;

        #pragma unroll
        for (int kk = 0; kk < BK; kk += 16) {
            uint32_t a[4][4];
            uint32_t b[8][2];
            #pragma unroll
            for (int i = 0; i < 4; i++) {
                int r = warpRow * 64 + i * 16 + (lane & 15);
                int c = kk + ((lane >> 4) << 3);
                uint32_t addr = stA + r * (SSTRIDE * 2) + c * 2;
                asm volatile("ldmatrix.sync.aligned.m8n8.x4.shared.b16 {%0,%1,%2,%3}, [%4];"
                             : "=r"(a[i][0]), "=r"(a[i][1]), "=r"(a[i][2]), "=r"(a[i][3])
                             : "r"(addr));
            }
            #pragma unroll
            for (int j = 0; j < 4; j++) {
                int r = warpCol * 64 + j * 16 + ((lane >> 4) << 3) + (lane & 7);
                int c = kk + (((lane >> 3) & 1) << 3);
                uint32_t addr = stB + r * (SSTRIDE * 2) + c * 2;
                asm volatile("ldmatrix.sync.aligned.m8n8.x4.shared.b16 {%0,%1,%2,%3}, [%4];"
                             : "=r"(b[2 * j][0]), "=r"(b[2 * j][1]),
                               "=r"(b[2 * j + 1][0]), "=r"(b[2 * j + 1][1])
                             : "r"(addr));
            }
            #pragma unroll
            for (int i = 0; i < 4; i++)
                #pragma unroll
                for (int j = 0; j < 8; j++)
                    asm volatile(
                        "mma.sync.aligned.m16n8k16.row.col.f32.bf16.bf16.f32 "
                        "{%0,%1,%2,%3}, {%4,%5,%6,%7}, {%8,%9}, {%0,%1,%2,%3};"
                        : "+f"(acc[i][j][0]), "+f"(acc[i][j][1]),
                          "+f"(acc[i][j][2]), "+f"(acc[i][j][3])
                        : "r"(a[i][0]), "r"(a[i][1]), "r"(a[i][2]), "r"(a[i][3]),
                          "r"(b[j][0]), "r"(b[j][1]));
        }
        __syncthreads();
    }

    // ---- Row maxes: fragment row = groupID(lane>>2) within each 8-row band.
    #pragma unroll
    for (int i = 0; i < 4; i++) {
        #pragma unroll
        for (int half = 0; half < 2; half++) {
            float m = -INFINITY;
            #pragma unroll
            for (int j = 0; j < 8; j++)
                m = fmaxf(m, fmaxf(acc[i][j][half * 2], acc[i][j][half * 2 + 1]));
            m = fmaxf(m, __shfl_xor_sync(0xffffffffu, m, 1));
            m = fmaxf(m, __shfl_xor_sync(0xffffffffu, m, 2));
            if ((lane & 3) == 0)
                atomicMaxF(&s_rmax[warpRow * 64 + i * 16 + half * 8 + (lane >> 2)], m);
        }
    }
    // ---- Col maxes: fragment col = (lane&3)*2 + q within each 8-col tile.
    #pragma unroll
    for (int j = 0; j < 8; j++) {
        #pragma unroll
        for (int q = 0; q < 2; q++) {
            float m = -INFINITY;
            #pragma unroll
            for (int i = 0; i < 4; i++)
                m = fmaxf(m, fmaxf(acc[i][j][q], acc[i][j][q + 2]));
            m = fmaxf(m, __shfl_xor_sync(0xffffffffu, m, 4));
            m = fmaxf(m, __shfl_xor_sync(0xffffffffu, m, 8));
            m = fmaxf(m, __shfl_xor_sync(0xffffffffu, m, 16));
            if (lane < 4)
                atomicMaxF(&s_cmax[warpCol * 64 + j * 8 + (lane & 3) * 2 + q], m);
        }
    }
    __syncthreads();
    if (tid < BM) atomicMaxF(&g_rowmax[rowBase + tid], s_rmax[tid]);
    atomicMaxF(&g_colmax[colBase + tid], s_cmax[tid]);
}

// ---------------------------------------------------------------------------
// Kernel 3: sum max vectors, entropy transform, write out[2].
// ---------------------------------------------------------------------------
__global__ void __launch_bounds__(256) finalize_kernel(float* __restrict__ out) {
    __shared__ float sh[16];
    int tid = threadIdx.x;
    float sr = 0.f, sc = 0.f;
    for (int i = tid; i < N_ROWS; i += 256) {
        sr += g_rowmax[i];
        sc += g_colmax[i];
    }
    #pragma unroll
    for (int o = 16; o; o >>= 1) {
        sr += __shfl_xor_sync(0xffffffffu, sr, o);
        sc += __shfl_xor_sync(0xffffffffu, sc, o);
    }
    if ((tid & 31) == 0) {
        sh[tid >> 5]       = sr;
        sh[8 + (tid >> 5)] = sc;
    }
    __syncthreads();
    if (tid == 0) {
        float SR = 0.f, SC = 0.f;
        #pragma unroll
        for (int w = 0; w < 8; w++) { SR += sh[w]; SC += sh[8 + w]; }
        const double sigma = 0.3;
        float hc = (float)(0.5 * log(6.283185307179586 * sigma * sigma) + 0.5);
        out[0] = hc * ((float)N_ROWS - SR) / 0.3f;
        out[1] = hc * ((float)N_ROWS - SC) / 0.3f;
    }
}

// ---------------------------------------------------------------------------
extern "C" void kernel_launch(void* const* d_in, const int* in_sizes, int n_in,
                              void* d_out, int out_size) {
    const float* ex = (const float*)d_in[0];
    const float* ey = (const float*)d_in[1];
    float* out = (float*)d_out;

    cudaFuncSetAttribute(gemm_max_kernel,
                         cudaFuncAttributeMaxDynamicSharedMemorySize, SMEM_DYN);

    init_kernel<<<(2 * N_ROWS) / 256, 256>>>();
    normalize_kernel<<<2 * N_ROWS, 256>>>(ex, ey);
    dim3 grid(N_ROWS / BN, N_ROWS / BM);
    gemm_max_kernel<<<grid, 256, SMEM_DYN>>>();
    finalize_kernel<<<1, 256>>>(out);
}

// round 6
// speedup vs baseline: 1.3297x; 1.0190x over previous
#include <cuda_runtime.h>
#include <cuda_bf16.h>
#include <cuda_fp8.h>
#include <math.h>
#include <stdint.h>

#define N_ROWS 8192
#define DIM    1024
#define BM     128          // CTA rows (ex)
#define BN     256          // CTA cols (ey)
#define BKB    128          // k bytes (fp8 elems) per pipeline chunk
#define NCHUNK (DIM / BKB)  // 8
#define NSTAGE 3
#define SSTRIDE_B 144       // padded bytes per smem row -> conflict-free ldmatrix
#define A_STAGE_BYTES (BM * SSTRIDE_B)                // 18432
#define B_STAGE_BYTES (BN * SSTRIDE_B)                // 36864
#define STAGE_BYTES   (A_STAGE_BYTES + B_STAGE_BYTES) // 55296
#define SMEM_PIPE     (NSTAGE * STAGE_BYTES)          // 165888
#define RMAX_OFF      SMEM_PIPE                       // 128 floats
#define CMAX_OFF      (SMEM_PIPE + 512)               // 256 floats
#define SMEM_DYN      (SMEM_PIPE + 512 + 1024)

#define SCALE 16.0f         // pre-quantization scale; dots carry 256x

// Scratch (no cudaMalloc allowed): fp8 normalized copies + max accumulators.
__device__ unsigned char g_exn8[(size_t)N_ROWS * DIM];
__device__ unsigned char g_eyn8[(size_t)N_ROWS * DIM];
__device__ float g_rowmax[N_ROWS];
__device__ float g_colmax[N_ROWS];

__device__ __forceinline__ void atomicMaxF(float* addr, float val) {
    if (__float_as_int(val) >= 0) {
        atomicMax(reinterpret_cast<int*>(addr), __float_as_int(val));
    } else {
        atomicMin(reinterpret_cast<unsigned int*>(addr), __float_as_uint(val));
    }
}

__device__ __forceinline__ void cp_async16(uint32_t s, const void* g) {
    asm volatile("cp.async.cg.shared.global [%0], [%1], 16;" :: "r"(s), "l"(g));
}
__device__ __forceinline__ void cp_commit() {
    asm volatile("cp.async.commit_group;" ::: "memory");
}
template <int N>
__device__ __forceinline__ void cp_wait() {
    asm volatile("cp.async.wait_group %0;" :: "n"(N) : "memory");
}

// ---------------------------------------------------------------------------
// Kernel 0: reset max accumulators
// ---------------------------------------------------------------------------
__global__ void init_kernel() {
    int i = blockIdx.x * blockDim.x + threadIdx.x;
    if (i < N_ROWS) g_rowmax[i] = -INFINITY;
    else            g_colmax[i - N_ROWS] = -INFINITY;
}

// ---------------------------------------------------------------------------
// Kernel 1: fp32 row L2-normalize, scale by 16, emit fp8 e4m3.
// ---------------------------------------------------------------------------
__global__ void __launch_bounds__(256) normalize_kernel(const float* __restrict__ ex,
                                                        const float* __restrict__ ey) {
    __shared__ float sh[8];
    int row = blockIdx.x;
    const float* src;
    unsigned char* dst;
    if (row < N_ROWS) {
        src = ex + (size_t)row * DIM;
        dst = g_exn8 + (size_t)row * DIM;
    } else {
        src = ey + (size_t)(row - N_ROWS) * DIM;
        dst = g_eyn8 + (size_t)(row - N_ROWS) * DIM;
    }
    int tid = threadIdx.x;
    float4 v = reinterpret_cast<const float4*>(src)[tid];
    float ss = v.x * v.x + v.y * v.y + v.z * v.z + v.w * v.w;
    #pragma unroll
    for (int o = 16; o; o >>= 1) ss += __shfl_xor_sync(0xffffffffu, ss, o);
    if ((tid & 31) == 0) sh[tid >> 5] = ss;
    __syncthreads();
    float tot = 0.f;
    #pragma unroll
    for (int w = 0; w < 8; w++) tot += sh[w];
    float inv = rsqrtf(tot) * SCALE;
    uint32_t b0 = __nv_cvt_float_to_fp8(v.x * inv, __NV_SATFINITE, __NV_E4M3);
    uint32_t b1 = __nv_cvt_float_to_fp8(v.y * inv, __NV_SATFINITE, __NV_E4M3);
    uint32_t b2 = __nv_cvt_float_to_fp8(v.z * inv, __NV_SATFINITE, __NV_E4M3);
    uint32_t b3 = __nv_cvt_float_to_fp8(v.w * inv, __NV_SATFINITE, __NV_E4M3);
    reinterpret_cast<uint32_t*>(dst)[tid] = b0 | (b1 << 8) | (b2 << 16) | (b3 << 24);
}

// ---------------------------------------------------------------------------
// Kernel 2: pipelined fp8 mma.sync GEMM (128x256 CTA tile), fused max-reduce.
// 8 warps: 2 warp-rows x 4 warp-cols; warp tile 64x64.
// 3-stage cp.async pipeline over BKB=128-byte k-chunks (k32 MMA steps).
// ---------------------------------------------------------------------------
__device__ __forceinline__ void load_chunk(uint32_t sbase, int s, int kc,
                                           int rowBase, int colBase, int tid) {
    uint32_t stA = sbase + s * STAGE_BYTES;
    uint32_t stB = stA + A_STAGE_BYTES;
    const unsigned char* gA = g_exn8 + (size_t)rowBase * DIM + kc * BKB;
    const unsigned char* gB = g_eyn8 + (size_t)colBase * DIM + kc * BKB;
    #pragma unroll
    for (int t = 0; t < 4; t++) {           // A: 128 rows x 128 bytes
        int idx = tid + t * 256;            // 0..1023
        int r = idx >> 3;                   // 0..127
        int c = idx & 7;                    // 16B unit
        cp_async16(stA + r * SSTRIDE_B + c * 16, gA + (size_t)r * DIM + c * 16);
    }
    #pragma unroll
    for (int t = 0; t < 8; t++) {           // B: 256 rows x 128 bytes
        int idx = tid + t * 256;            // 0..2047
        int r = idx >> 3;                   // 0..255
        int c = idx & 7;
        cp_async16(stB + r * SSTRIDE_B + c * 16, gB + (size_t)r * DIM + c * 16);
    }
}

__global__ void __launch_bounds__(256, 1) gemm_max_kernel() {
    extern __shared__ char dsm[];
    const int tid  = threadIdx.x;
    const int lane = tid & 31;
    const int wid  = tid >> 5;
    const int warpRow = wid & 1;      // 0..1 -> 64-row slab
    const int warpCol = wid >> 1;     // 0..3 -> 64-col slab
    const int rowBase = blockIdx.y * BM;
    const int colBase = blockIdx.x * BN;

    uint32_t sbase = (uint32_t)__cvta_generic_to_shared(dsm);
    float* s_rmax = reinterpret_cast<float*>(dsm + RMAX_OFF);
    float* s_cmax = reinterpret_cast<float*>(dsm + CMAX_OFF);
    if (tid < BM) s_rmax[tid] = -INFINITY;
    s_cmax[tid] = -INFINITY;

    float acc[4][8][4];
    #pragma unroll
    for (int i = 0; i < 4; i++)
        #pragma unroll
        for (int j = 0; j < 8; j++)
            #pragma unroll
            for (int r = 0; r < 4; r++) acc[i][j][r] = 0.f;

    load_chunk(sbase, 0, 0, rowBase, colBase, tid); cp_commit();
    load_chunk(sbase, 1, 1, rowBase, colBase, tid); cp_commit();

    for (int ch = 0; ch < NCHUNK; ch++) {
        int s = ch % NSTAGE;
        if (ch < NCHUNK - 1) cp_wait<1>(); else cp_wait<0>();
        __syncthreads();

        if (ch + 2 < NCHUNK) {
            load_chunk(sbase, (ch + 2) % NSTAGE, ch + 2, rowBase, colBase, tid);
            cp_commit();
        }

        uint32_t stA = sbase + s * STAGE_BYTES;
        uint32_t stB = stA + A_STAGE_BYTES;

        #pragma unroll
        for (int kk = 0; kk < 4; kk++) {     // 4 x k32 steps per 128B chunk
            uint32_t a[4][4];
            uint32_t b[8][2];
            // A fragments: m16 x k32 per x4 ldmatrix.
            // lane -> row: +8 if (lane>>3)&1 ; kbyte: +16 if lane>=16
            #pragma unroll
            for (int i = 0; i < 4; i++) {
                int r  = warpRow * 64 + i * 16 + ((lane >> 3) & 1) * 8 + (lane & 7);
                int kb = kk * 32 + (lane >> 4) * 16;
                uint32_t addr = stA + r * SSTRIDE_B + kb;
                asm volatile("ldmatrix.sync.aligned.m8n8.x4.shared.b16 {%0,%1,%2,%3}, [%4];"
                             : "=r"(a[i][0]), "=r"(a[i][1]), "=r"(a[i][2]), "=r"(a[i][3])
                             : "r"(addr));
            }
            // B fragments: two n8 tiles per x4 ldmatrix.
            // block b = lane>>3: n_off = (b>>1)*8, kbyte_off = (b&1)*16
            #pragma unroll
            for (int j = 0; j < 4; j++) {
                int n  = warpCol * 64 + j * 16 + (lane >> 4) * 8 + (lane & 7);
                int kb = kk * 32 + ((lane >> 3) & 1) * 16;
                uint32_t addr = stB + n * SSTRIDE_B + kb;
                asm volatile("ldmatrix.sync.aligned.m8n8.x4.shared.b16 {%0,%1,%2,%3}, [%4];"
                             : "=r"(b[2 * j][0]), "=r"(b[2 * j][1]),
                               "=r"(b[2 * j + 1][0]), "=r"(b[2 * j + 1][1])
                             : "r"(addr));
            }
            #pragma unroll
            for (int i = 0; i < 4; i++)
                #pragma unroll
                for (int j = 0; j < 8; j++)
                    asm volatile(
                        "mma.sync.aligned.m16n8k32.row.col.f32.e4m3.e4m3.f32 "
                        "{%0,%1,%2,%3}, {%4,%5,%6,%7}, {%8,%9}, {%0,%1,%2,%3};"
                        : "+f"(acc[i][j][0]), "+f"(acc[i][j][1]),
                          "+f"(acc[i][j][2]), "+f"(acc[i][j][3])
                        : "r"(a[i][0]), "r"(a[i][1]), "r"(a[i][2]), "r"(a[i][3]),
                          "r"(b[j][0]), "r"(b[j][1]));
        }
        __syncthreads();
    }

    // ---- Row maxes (acc carries 256x cosine; rescaled in finalize) ----
    #pragma unroll
    for (int i = 0; i < 4; i++) {
        #pragma unroll
        for (int half = 0; half < 2; half++) {
            float m = -INFINITY;
            #pragma unroll
            for (int j = 0; j < 8; j++)
                m = fmaxf(m, fmaxf(acc[i][j][half * 2], acc[i][j][half * 2 + 1]));
            m = fmaxf(m, __shfl_xor_sync(0xffffffffu, m, 1));
            m = fmaxf(m, __shfl_xor_sync(0xffffffffu, m, 2));
            if ((lane & 3) == 0)
                atomicMaxF(&s_rmax[warpRow * 64 + i * 16 + half * 8 + (lane >> 2)], m);
        }
    }
    // ---- Col maxes ----
    #pragma unroll
    for (int j = 0; j < 8; j++) {
        #pragma unroll
        for (int q = 0; q < 2; q++) {
            float m = -INFINITY;
            #pragma unroll
            for (int i = 0; i < 4; i++)
                m = fmaxf(m, fmaxf(acc[i][j][q], acc[i][j][q + 2]));
            m = fmaxf(m, __shfl_xor_sync(0xffffffffu, m, 4));
            m = fmaxf(m, __shfl_xor_sync(0xffffffffu, m, 8));
            m = fmaxf(m, __shfl_xor_sync(0xffffffffu, m, 16));
            if (lane < 4)
                atomicMaxF(&s_cmax[warpCol * 64 + j * 8 + (lane & 3) * 2 + q], m);
        }
    }
    __syncthreads();
    if (tid < BM) atomicMaxF(&g_rowmax[rowBase + tid], s_rmax[tid]);
    atomicMaxF(&g_colmax[colBase + tid], s_cmax[tid]);
}

// ---------------------------------------------------------------------------
// Kernel 3: sum max vectors (undo 256x scale), entropy transform, out[2].
// ---------------------------------------------------------------------------
__global__ void __launch_bounds__(256) finalize_kernel(float* __restrict__ out) {
    __shared__ float sh[16];
    int tid = threadIdx.x;
    float sr = 0.f, sc = 0.f;
    for (int i = tid; i < N_ROWS; i += 256) {
        sr += g_rowmax[i];
        sc += g_colmax[i];
    }
    #pragma unroll
    for (int o = 16; o; o >>= 1) {
        sr += __shfl_xor_sync(0xffffffffu, sr, o);
        sc += __shfl_xor_sync(0xffffffffu, sc, o);
    }
    if ((tid & 31) == 0) {
        sh[tid >> 5]       = sr;
        sh[8 + (tid >> 5)] = sc;
    }
    __syncthreads();
    if (tid == 0) {
        float SR = 0.f, SC = 0.f;
        #pragma unroll
        for (int w = 0; w < 8; w++) { SR += sh[w]; SC += sh[8 + w]; }
        const float invs2 = 1.0f / (SCALE * SCALE);
        const double sigma = 0.3;
        float hc = (float)(0.5 * log(6.283185307179586 * sigma * sigma) + 0.5);
        out[0] = hc * ((float)N_ROWS - SR * invs2) / 0.3f;
        out[1] = hc * ((float)N_ROWS - SC * invs2) / 0.3f;
    }
}

// ---------------------------------------------------------------------------
extern "C" void kernel_launch(void* const* d_in, const int* in_sizes, int n_in,
                              void* d_out, int out_size) {
    const float* ex = (const float*)d_in[0];
    const float* ey = (const float*)d_in[1];
    float* out = (float*)d_out;

    cudaFuncSetAttribute(gemm_max_kernel,
                         cudaFuncAttributeMaxDynamicSharedMemorySize, SMEM_DYN);

    init_kernel<<<(2 * N_ROWS) / 256, 256>>>();
    normalize_kernel<<<2 * N_ROWS, 256>>>(ex, ey);
    dim3 grid(N_ROWS / BN, N_ROWS / BM);
    gemm_max_kernel<<<grid, 256, SMEM_DYN>>>();
    finalize_kernel<<<1, 256>>>(out);
}

// round 7
// speedup vs baseline: 1.4425x; 1.0848x over previous
#include <cuda_runtime.h>
#include <cuda_bf16.h>
#include <cuda_fp8.h>
#include <math.h>
#include <stdint.h>

#define N_ROWS 8192
#define DIM    1024
#define BM     128          // CTA rows (ex)
#define BN     128          // CTA cols (ey)
#define BKB    128          // k bytes (fp8 elems) per pipeline chunk
#define NCHUNK (DIM / BKB)  // 8
#define NSTAGE 3
#define SSTRIDE_B 144       // padded bytes per smem row -> conflict-free ldmatrix
#define A_STAGE_BYTES (BM * SSTRIDE_B)                // 18432
#define B_STAGE_BYTES (BN * SSTRIDE_B)                // 18432
#define STAGE_BYTES   (A_STAGE_BYTES + B_STAGE_BYTES) // 36864
#define SMEM_PIPE     (NSTAGE * STAGE_BYTES)          // 110592
#define RMAX_OFF      SMEM_PIPE                       // 128 floats
#define CMAX_OFF      (SMEM_PIPE + 512)               // 128 floats
#define SMEM_DYN      (SMEM_PIPE + 1024)              // 111616 -> 2 CTAs/SM

#define SCALE 16.0f         // pre-quantization scale; dots carry 256x

// Scratch (no cudaMalloc allowed): fp8 normalized copies + max accumulators.
__device__ unsigned char g_exn8[(size_t)N_ROWS * DIM];
__device__ unsigned char g_eyn8[(size_t)N_ROWS * DIM];
__device__ float g_rowmax[N_ROWS];
__device__ float g_colmax[N_ROWS];

__device__ __forceinline__ void atomicMaxF(float* addr, float val) {
    if (__float_as_int(val) >= 0) {
        atomicMax(reinterpret_cast<int*>(addr), __float_as_int(val));
    } else {
        atomicMin(reinterpret_cast<unsigned int*>(addr), __float_as_uint(val));
    }
}

__device__ __forceinline__ void cp_async16(uint32_t s, const void* g) {
    asm volatile("cp.async.cg.shared.global [%0], [%1], 16;" :: "r"(s), "l"(g));
}
__device__ __forceinline__ void cp_commit() {
    asm volatile("cp.async.commit_group;" ::: "memory");
}
template <int N>
__device__ __forceinline__ void cp_wait() {
    asm volatile("cp.async.wait_group %0;" :: "n"(N) : "memory");
}

// ---------------------------------------------------------------------------
// Kernel 0: reset max accumulators
// ---------------------------------------------------------------------------
__global__ void init_kernel() {
    int i = blockIdx.x * blockDim.x + threadIdx.x;
    if (i < N_ROWS) g_rowmax[i] = -INFINITY;
    else            g_colmax[i - N_ROWS] = -INFINITY;
}

// ---------------------------------------------------------------------------
// Kernel 1: fp32 row L2-normalize, scale by 16, emit fp8 e4m3.
// ---------------------------------------------------------------------------
__global__ void __launch_bounds__(256) normalize_kernel(const float* __restrict__ ex,
                                                        const float* __restrict__ ey) {
    __shared__ float sh[8];
    int row = blockIdx.x;
    const float* src;
    unsigned char* dst;
    if (row < N_ROWS) {
        src = ex + (size_t)row * DIM;
        dst = g_exn8 + (size_t)row * DIM;
    } else {
        src = ey + (size_t)(row - N_ROWS) * DIM;
        dst = g_eyn8 + (size_t)(row - N_ROWS) * DIM;
    }
    int tid = threadIdx.x;
    float4 v = reinterpret_cast<const float4*>(src)[tid];
    float ss = v.x * v.x + v.y * v.y + v.z * v.z + v.w * v.w;
    #pragma unroll
    for (int o = 16; o; o >>= 1) ss += __shfl_xor_sync(0xffffffffu, ss, o);
    if ((tid & 31) == 0) sh[tid >> 5] = ss;
    __syncthreads();
    float tot = 0.f;
    #pragma unroll
    for (int w = 0; w < 8; w++) tot += sh[w];
    float inv = rsqrtf(tot) * SCALE;
    uint32_t b0 = __nv_cvt_float_to_fp8(v.x * inv, __NV_SATFINITE, __NV_E4M3);
    uint32_t b1 = __nv_cvt_float_to_fp8(v.y * inv, __NV_SATFINITE, __NV_E4M3);
    uint32_t b2 = __nv_cvt_float_to_fp8(v.z * inv, __NV_SATFINITE, __NV_E4M3);
    uint32_t b3 = __nv_cvt_float_to_fp8(v.w * inv, __NV_SATFINITE, __NV_E4M3);
    reinterpret_cast<uint32_t*>(dst)[tid] = b0 | (b1 << 8) | (b2 << 16) | (b3 << 24);
}

// ---------------------------------------------------------------------------
// Kernel 2: pipelined fp8 mma.sync GEMM (128x128 CTA tile), fused max-reduce.
// 8 warps: 4 warp-rows x 2 warp-cols; warp tile 32x64.
// 2 CTAs/SM (111.6KB smem) -> 4 warps/SMSP to hide legacy-MMA pipe latency.
// ---------------------------------------------------------------------------
__device__ __forceinline__ void load_chunk(uint32_t sbase, int s, int kc,
                                           int rowBase, int colBase, int tid) {
    uint32_t stA = sbase + s * STAGE_BYTES;
    uint32_t stB = stA + A_STAGE_BYTES;
    const unsigned char* gA = g_exn8 + (size_t)rowBase * DIM + kc * BKB;
    const unsigned char* gB = g_eyn8 + (size_t)colBase * DIM + kc * BKB;
    #pragma unroll
    for (int t = 0; t < 4; t++) {           // A: 128 rows x 128 bytes
        int idx = tid + t * 256;            // 0..1023
        int r = idx >> 3;                   // 0..127
        int c = idx & 7;                    // 16B unit
        cp_async16(stA + r * SSTRIDE_B + c * 16, gA + (size_t)r * DIM + c * 16);
    }
    #pragma unroll
    for (int t = 0; t < 4; t++) {           // B: 128 rows x 128 bytes
        int idx = tid + t * 256;
        int r = idx >> 3;
        int c = idx & 7;
        cp_async16(stB + r * SSTRIDE_B + c * 16, gB + (size_t)r * DIM + c * 16);
    }
}

__global__ void __launch_bounds__(256, 2) gemm_max_kernel() {
    extern __shared__ char dsm[];
    const int tid  = threadIdx.x;
    const int lane = tid & 31;
    const int wid  = tid >> 5;
    const int warpRow = wid & 3;      // 0..3 -> 32-row slab
    const int warpCol = wid >> 2;     // 0..1 -> 64-col slab
    const int rowBase = blockIdx.y * BM;
    const int colBase = blockIdx.x * BN;

    uint32_t sbase = (uint32_t)__cvta_generic_to_shared(dsm);
    float* s_rmax = reinterpret_cast<float*>(dsm + RMAX_OFF);
    float* s_cmax = reinterpret_cast<float*>(dsm + CMAX_OFF);
    if (tid < BM) s_rmax[tid] = -INFINITY;
    if (tid < BN) s_cmax[tid] = -INFINITY;

    float acc[2][8][4];
    #pragma unroll
    for (int i = 0; i < 2; i++)
        #pragma unroll
        for (int j = 0; j < 8; j++)
            #pragma unroll
            for (int r = 0; r < 4; r++) acc[i][j][r] = 0.f;

    load_chunk(sbase, 0, 0, rowBase, colBase, tid); cp_commit();
    load_chunk(sbase, 1, 1, rowBase, colBase, tid); cp_commit();

    for (int ch = 0; ch < NCHUNK; ch++) {
        int s = ch % NSTAGE;
        if (ch < NCHUNK - 1) cp_wait<1>(); else cp_wait<0>();
        __syncthreads();

        if (ch + 2 < NCHUNK) {
            load_chunk(sbase, (ch + 2) % NSTAGE, ch + 2, rowBase, colBase, tid);
            cp_commit();
        }

        uint32_t stA = sbase + s * STAGE_BYTES;
        uint32_t stB = stA + A_STAGE_BYTES;

        #pragma unroll
        for (int kk = 0; kk < 4; kk++) {     // 4 x k32 steps per 128B chunk
            uint32_t a[2][4];
            uint32_t b[8][2];
            // A fragments: m16 x k32 per x4 ldmatrix.
            #pragma unroll
            for (int i = 0; i < 2; i++) {
                int r  = warpRow * 32 + i * 16 + ((lane >> 3) & 1) * 8 + (lane & 7);
                int kb = kk * 32 + (lane >> 4) * 16;
                uint32_t addr = stA + r * SSTRIDE_B + kb;
                asm volatile("ldmatrix.sync.aligned.m8n8.x4.shared.b16 {%0,%1,%2,%3}, [%4];"
                             : "=r"(a[i][0]), "=r"(a[i][1]), "=r"(a[i][2]), "=r"(a[i][3])
                             : "r"(addr));
            }
            // B fragments: two n8 k32 tiles per x4 ldmatrix.
            #pragma unroll
            for (int j = 0; j < 4; j++) {
                int n  = warpCol * 64 + j * 16 + (lane >> 4) * 8 + (lane & 7);
                int kb = kk * 32 + ((lane >> 3) & 1) * 16;
                uint32_t addr = stB + n * SSTRIDE_B + kb;
                asm volatile("ldmatrix.sync.aligned.m8n8.x4.shared.b16 {%0,%1,%2,%3}, [%4];"
                             : "=r"(b[2 * j][0]), "=r"(b[2 * j][1]),
                               "=r"(b[2 * j + 1][0]), "=r"(b[2 * j + 1][1])
                             : "r"(addr));
            }
            #pragma unroll
            for (int i = 0; i < 2; i++)
                #pragma unroll
                for (int j = 0; j < 8; j++)
                    asm volatile(
                        "mma.sync.aligned.m16n8k32.row.col.f32.e4m3.e4m3.f32 "
                        "{%0,%1,%2,%3}, {%4,%5,%6,%7}, {%8,%9}, {%0,%1,%2,%3};"
                        : "+f"(acc[i][j][0]), "+f"(acc[i][j][1]),
                          "+f"(acc[i][j][2]), "+f"(acc[i][j][3])
                        : "r"(a[i][0]), "r"(a[i][1]), "r"(a[i][2]), "r"(a[i][3]),
                          "r"(b[j][0]), "r"(b[j][1]));
        }
        __syncthreads();
    }

    // ---- Row maxes (acc carries 256x cosine; rescaled in finalize) ----
    #pragma unroll
    for (int i = 0; i < 2; i++) {
        #pragma unroll
        for (int half = 0; half < 2; half++) {
            float m = -INFINITY;
            #pragma unroll
            for (int j = 0; j < 8; j++)
                m = fmaxf(m, fmaxf(acc[i][j][half * 2], acc[i][j][half * 2 + 1]));
            m = fmaxf(m, __shfl_xor_sync(0xffffffffu, m, 1));
            m = fmaxf(m, __shfl_xor_sync(0xffffffffu, m, 2));
            if ((lane & 3) == 0)
                atomicMaxF(&s_rmax[warpRow * 32 + i * 16 + half * 8 + (lane >> 2)], m);
        }
    }
    // ---- Col maxes ----
    #pragma unroll
    for (int j = 0; j < 8; j++) {
        #pragma unroll
        for (int q = 0; q < 2; q++) {
            float m = -INFINITY;
            #pragma unroll
            for (int i = 0; i < 2; i++)
                m = fmaxf(m, fmaxf(acc[i][j][q], acc[i][j][q + 2]));
            m = fmaxf(m, __shfl_xor_sync(0xffffffffu, m, 4));
            m = fmaxf(m, __shfl_xor_sync(0xffffffffu, m, 8));
            m = fmaxf(m, __shfl_xor_sync(0xffffffffu, m, 16));
            if (lane < 4)
                atomicMaxF(&s_cmax[warpCol * 64 + j * 8 + (lane & 3) * 2 + q], m);
        }
    }
    __syncthreads();
    if (tid < BM) atomicMaxF(&g_rowmax[rowBase + tid], s_rmax[tid]);
    if (tid < BN) atomicMaxF(&g_colmax[colBase + tid], s_cmax[tid]);
}

// ---------------------------------------------------------------------------
// Kernel 3: sum max vectors (undo 256x scale), entropy transform, out[2].
// ---------------------------------------------------------------------------
__global__ void __launch_bounds__(256) finalize_kernel(float* __restrict__ out) {
    __shared__ float sh[16];
    int tid = threadIdx.x;
    float sr = 0.f, sc = 0.f;
    for (int i = tid; i < N_ROWS; i += 256) {
        sr += g_rowmax[i];
        sc += g_colmax[i];
    }
    #pragma unroll
    for (int o = 16; o; o >>= 1) {
        sr += __shfl_xor_sync(0xffffffffu, sr, o);
        sc += __shfl_xor_sync(0xffffffffu, sc, o);
    }
    if ((tid & 31) == 0) {
        sh[tid >> 5]       = sr;
        sh[8 + (tid >> 5)] = sc;
    }
    __syncthreads();
    if (tid == 0) {
        float SR = 0.f, SC = 0.f;
        #pragma unroll
        for (int w = 0; w < 8; w++) { SR += sh[w]; SC += sh[8 + w]; }
        const float invs2 = 1.0f / (SCALE * SCALE);
        const double sigma = 0.3;
        float hc = (float)(0.5 * log(6.283185307179586 * sigma * sigma) + 0.5);
        out[0] = hc * ((float)N_ROWS - SR * invs2) / 0.3f;
        out[1] = hc * ((float)N_ROWS - SC * invs2) / 0.3f;
    }
}

// ---------------------------------------------------------------------------
extern "C" void kernel_launch(void* const* d_in, const int* in_sizes, int n_in,
                              void* d_out, int out_size) {
    const float* ex = (const float*)d_in[0];
    const float* ey = (const float*)d_in[1];
    float* out = (float*)d_out;

    cudaFuncSetAttribute(gemm_max_kernel,
                         cudaFuncAttributeMaxDynamicSharedMemorySize, SMEM_DYN);

    init_kernel<<<(2 * N_ROWS) / 256, 256>>>();
    normalize_kernel<<<2 * N_ROWS, 256>>>(ex, ey);
    dim3 grid(N_ROWS / BN, N_ROWS / BM);
    gemm_max_kernel<<<grid, 256, SMEM_DYN>>>();
    finalize_kernel<<<1, 256>>>(out);
}